// round 14
// baseline (speedup 1.0000x reference)
#include <cuda_runtime.h>
#include <cuda_bf16.h>
#include <cstdint>

// Problem constants
#define N_NODES 100000
#define N_EDGES 1638400
#define IN_CH   128
#define HEADS   4
#define OUT_CH  32
#define OUTF    (HEADS * OUT_CH)   // 128

// Scratch (allowed: __device__ globals, no allocation)
__device__ float g_h [(size_t)N_NODES * OUTF];   // 51.2 MB, L2-resident
__device__ float g_al[(size_t)N_NODES * HEADS];
__device__ float g_ar[(size_t)N_NODES * HEADS];

// ===========================================================================
// Kernel 1: h = x @ W^T + b via mma.sync bf16 3-term split.
//   h = x_hi*W_hi + x_hi*W_lo + x_lo*W_hi  (fp32 accumulate)
// CTA: 128 rows x 128 cols, full K=128 resident in smem bf16 tiles.
// 512 threads / 16 warps (4 per SMSP — latency hiding was the R13 binder);
// warp tile 32x32 = 2x4 grid of m16n8k16 fragments.
// Epilogue stages D in smem; thread=(row,head) fuses bias + alpha dots.
// ===========================================================================
#define GBM 128
#define ASTR 272            // bf16 tile row stride in bytes (136 bf16) — conflict-free
#define TILE_BYTES (128 * ASTR)   // 34816

// dynamic smem layout (bytes)
#define SO_BIAS 0
#define SO_ATTL 512
#define SO_ATTR 1024
#define SO_AHI  1536
#define SO_ALO  (SO_AHI + TILE_BYTES)
#define SO_WHI  (SO_ALO + TILE_BYTES)
#define SO_WLO  (SO_WHI + TILE_BYTES)
#define GEMM_SMEM_BYTES (SO_WLO + TILE_BYTES)   // 140800
#define DS 132              // D staging row stride (floats), overlays SO_AHI

__device__ __forceinline__ void mma_bf16_16816(float d[4],
                                               uint32_t a0, uint32_t a1,
                                               uint32_t a2, uint32_t a3,
                                               uint32_t b0, uint32_t b1) {
    asm volatile(
        "mma.sync.aligned.m16n8k16.row.col.f32.bf16.bf16.f32 "
        "{%0,%1,%2,%3}, {%4,%5,%6,%7}, {%8,%9}, {%0,%1,%2,%3};"
        : "+f"(d[0]), "+f"(d[1]), "+f"(d[2]), "+f"(d[3])
        : "r"(a0), "r"(a1), "r"(a2), "r"(a3), "r"(b0), "r"(b1));
}

__device__ __forceinline__ uint32_t lds32(const char* p) {
    return *reinterpret_cast<const uint32_t*>(p);
}

// convert 8 floats -> bf16 hi/lo packed uint4s
__device__ __forceinline__ void cvt_hilo8(const float* f, uint4& hiv, uint4& lov) {
    uint32_t hi[4], lo[4];
    #pragma unroll
    for (int j = 0; j < 4; j++) {
        __nv_bfloat162 h2 = __floats2bfloat162_rn(f[2*j], f[2*j+1]);
        float2 hf = __bfloat1622float2(h2);
        __nv_bfloat162 l2 = __floats2bfloat162_rn(f[2*j] - hf.x, f[2*j+1] - hf.y);
        hi[j] = *reinterpret_cast<uint32_t*>(&h2);
        lo[j] = *reinterpret_cast<uint32_t*>(&l2);
    }
    hiv = make_uint4(hi[0], hi[1], hi[2], hi[3]);
    lov = make_uint4(lo[0], lo[1], lo[2], lo[3]);
}

__global__ void __launch_bounds__(512)
gat_gemm_hmma(const float* __restrict__ x,
              const float* __restrict__ W,
              const float* __restrict__ b,
              const float* __restrict__ att_l,
              const float* __restrict__ att_r,
              int nrows)
{
    extern __shared__ char smem[];
    const int tid  = threadIdx.x;
    const int row0 = blockIdx.x * GBM;

    // ---- params to smem ----
    if (tid < 128) {
        ((float*)(smem + SO_BIAS))[tid] = b[tid];
        ((float*)(smem + SO_ATTL))[tid] = att_l[tid];
        ((float*)(smem + SO_ATTR))[tid] = att_r[tid];
    }

    // ---- convert to bf16 hi/lo: 512 threads, 1:1 work items ----
    // items [0,256):  x  (row, half-of-K)
    // items [256,512): W  (row, half-of-K)
    {
        const bool isW = (tid >= 256);
        const int  it  = isW ? (tid - 256) : tid;
        const int  row = it >> 1;
        const int  half = it & 1;
        const int  grow = row0 + row;
        const bool valid = isW || (grow < nrows);
        const float* srcp = isW ? (W + (size_t)row * IN_CH)
                                : (x + (size_t)grow * IN_CH);
        char* hi_base = smem + (isW ? SO_WHI : SO_AHI);
        char* lo_base = smem + (isW ? SO_WLO : SO_ALO);

        #pragma unroll
        for (int i = 0; i < 8; i++) {
            const int k0 = half * 64 + i * 8;
            float f[8];
            if (valid) {
                const float4* p = reinterpret_cast<const float4*>(srcp + k0);
                float4 v0 = p[0], v1 = p[1];
                f[0]=v0.x; f[1]=v0.y; f[2]=v0.z; f[3]=v0.w;
                f[4]=v1.x; f[5]=v1.y; f[6]=v1.z; f[7]=v1.w;
            } else {
                #pragma unroll
                for (int j = 0; j < 8; j++) f[j] = 0.f;
            }
            uint4 hiv, lov;
            cvt_hilo8(f, hiv, lov);
            const int off = row * ASTR + k0 * 2;   // 16B aligned
            *reinterpret_cast<uint4*>(hi_base + off) = hiv;
            *reinterpret_cast<uint4*>(lo_base + off) = lov;
        }
    }
    __syncthreads();

    // ---- MMA mainloop: 16 warps, warp tile 32x32 ----
    const int wid  = tid >> 5;
    const int lane = tid & 31;
    const int wm = (wid & 3) * 32;        // warp m origin (4 groups)
    const int wn = (wid >> 2) * 32;       // warp n origin (4 groups)
    const int gr = lane >> 2;             // 0..7
    const int kq = (lane & 3) * 2;        // 0,2,4,6

    float d[2][4][4];
    #pragma unroll
    for (int mt = 0; mt < 2; mt++)
        #pragma unroll
        for (int nt = 0; nt < 4; nt++)
            #pragma unroll
            for (int e = 0; e < 4; e++) d[mt][nt][e] = 0.f;

    #pragma unroll
    for (int s = 0; s < 3; s++) {
        const char* As = smem + ((s == 2) ? SO_ALO : SO_AHI);
        const char* Bs = smem + ((s == 1) ? SO_WLO : SO_WHI);
        #pragma unroll
        for (int ks = 0; ks < 8; ks++) {
            const int k0 = ks * 16;
            uint32_t a[2][4], bb[4][2];
            #pragma unroll
            for (int mt = 0; mt < 2; mt++) {
                const int m = wm + mt * 16;
                a[mt][0] = lds32(As + (m + gr    ) * ASTR + (k0 + kq    ) * 2);
                a[mt][1] = lds32(As + (m + gr + 8) * ASTR + (k0 + kq    ) * 2);
                a[mt][2] = lds32(As + (m + gr    ) * ASTR + (k0 + kq + 8) * 2);
                a[mt][3] = lds32(As + (m + gr + 8) * ASTR + (k0 + kq + 8) * 2);
            }
            #pragma unroll
            for (int nt = 0; nt < 4; nt++) {
                const int n = wn + nt * 8 + gr;
                bb[nt][0] = lds32(Bs + n * ASTR + (k0 + kq    ) * 2);
                bb[nt][1] = lds32(Bs + n * ASTR + (k0 + kq + 8) * 2);
            }
            #pragma unroll
            for (int mt = 0; mt < 2; mt++)
                #pragma unroll
                for (int nt = 0; nt < 4; nt++)
                    mma_bf16_16816(d[mt][nt], a[mt][0], a[mt][1], a[mt][2], a[mt][3],
                                   bb[nt][0], bb[nt][1]);
        }
    }
    __syncthreads();   // A/W tiles dead; stage D over SO_AHI region

    float* Dst = (float*)(smem + SO_AHI);   // [128][DS]
    #pragma unroll
    for (int mt = 0; mt < 2; mt++) {
        #pragma unroll
        for (int nt = 0; nt < 4; nt++) {
            const int r = wm + mt * 16 + gr;
            const int c = wn + nt * 8 + kq;
            *reinterpret_cast<float2*>(Dst + r * DS + c)       = make_float2(d[mt][nt][0], d[mt][nt][1]);
            *reinterpret_cast<float2*>(Dst + (r + 8) * DS + c) = make_float2(d[mt][nt][2], d[mt][nt][3]);
        }
    }
    __syncthreads();

    // ---- epilogue: thread = (row, head); bias add, g_h store, alpha dots ----
    {
        const int row  = tid >> 2;
        const int head = tid & 3;
        const int grow = row0 + row;
        if (grow < nrows) {
            const float* sbias = (const float*)(smem + SO_BIAS);
            const float* sattl = (const float*)(smem + SO_ATTL);
            const float* sattr = (const float*)(smem + SO_ATTR);
            float sl = 0.f, sr = 0.f;
            #pragma unroll
            for (int q = 0; q < 8; q++) {          // 8 float4 chunks = 32 cols
                float4 v;
                float* vp = &v.x;
                #pragma unroll
                for (int e = 0; e < 4; e++) {
                    const int gc = head * 32 + q * 4 + e;
                    float val = Dst[row * DS + gc] + sbias[gc];
                    vp[e] = val;
                    sl += val * sattl[gc];
                    sr += val * sattr[gc];
                }
                *reinterpret_cast<float4*>(g_h + (size_t)grow * OUTF + head * 32 + q * 4) = v;
            }
            g_al[(size_t)grow * HEADS + head] = sl;
            g_ar[(size_t)grow * HEADS + head] = sr;
        }
    }
}

// ===========================================================================
// Kernel 2: edge lift — exact R10 configuration (measured 186-190us):
// persistent grid-stride, 8 edges/warp/iter, plain __ldg gathers,
// __ldcs index loads, .cs streaming output stores, 4 CTAs/SM.
// ===========================================================================
#define EPW 8   // edges per warp per iteration (N_EDGES % EPW == 0)

__global__ void __launch_bounds__(256, 4)
edge_lift_kernel(const int* __restrict__ src_idx,
                 const int* __restrict__ trg_idx,
                 float* __restrict__ out_alpha,
                 float* __restrict__ out_x,
                 int nedges)
{
    const int lane   = threadIdx.x & 31;
    const int nwarps = (gridDim.x * blockDim.x) >> 5;
    const int gw     = (blockIdx.x * blockDim.x + threadIdx.x) >> 5;

    for (long long base = (long long)gw * EPW; base < nedges;
         base += (long long)nwarps * EPW) {

        int sidx = 0, tidx = 0;
        if (lane < EPW) {
            sidx = __ldcs(src_idx + base + lane);   // streaming: read-once
            tidx = __ldcs(trg_idx + base + lane);
        }

        int s[EPW];
        #pragma unroll
        for (int u = 0; u < EPW; u++)
            s[u] = __shfl_sync(0xffffffffu, sidx, u);

        // EPW independent gathers (MLP=EPW), L2-resident g_h
        float4 v[EPW];
        #pragma unroll
        for (int u = 0; u < EPW; u++)
            v[u] = *reinterpret_cast<const float4*>(g_h + (size_t)s[u] * OUTF + lane * 4);

        #pragma unroll
        for (int u = 0; u < EPW; u++)
            __stcs(reinterpret_cast<float4*>(out_x + (base + u) * OUTF + lane * 4), v[u]);

        if (lane < EPW) {
            float4 al = *reinterpret_cast<const float4*>(g_al + (size_t)sidx * HEADS);
            float4 ar = *reinterpret_cast<const float4*>(g_ar + (size_t)tidx * HEADS);
            float4 a;
            a.x = al.x + ar.x; a.x = (a.x >= 0.f) ? a.x : 0.01f * a.x;
            a.y = al.y + ar.y; a.y = (a.y >= 0.f) ? a.y : 0.01f * a.y;
            a.z = al.z + ar.z; a.z = (a.z >= 0.f) ? a.z : 0.01f * a.z;
            a.w = al.w + ar.w; a.w = (a.w >= 0.f) ? a.w : 0.01f * a.w;
            __stcs(reinterpret_cast<float4*>(out_alpha + (base + lane) * HEADS), a);
        }
    }
}

// ---------------------------------------------------------------------------
// Launch
// ---------------------------------------------------------------------------
extern "C" void kernel_launch(void* const* d_in, const int* in_sizes, int n_in,
                              void* d_out, int out_size)
{
    const float* x     = (const float*)d_in[0];   // [N, 128]
    const float* W     = (const float*)d_in[1];   // [128, 128]
    const float* b     = (const float*)d_in[2];   // [128]
    const float* att_l = (const float*)d_in[3];   // [1,4,32] -> flat 128
    const float* att_r = (const float*)d_in[4];   // [1,4,32] -> flat 128
    const int*   src   = (const int*)d_in[5];     // [E]
    const int*   trg   = (const int*)d_in[6];     // [E]

    float* out_alpha = (float*)d_out;                                   // [E, 4]
    float* out_x     = (float*)d_out + (size_t)N_EDGES * HEADS;         // [E, 4, 32]

    // >48KB dynamic smem opt-in (idempotent; harmless outside capture)
    cudaFuncSetAttribute(gat_gemm_hmma,
                         cudaFuncAttributeMaxDynamicSharedMemorySize,
                         GEMM_SMEM_BYTES);

    // 1) HMMA projection GEMM into g_h (+ fused alpha_l/alpha_r)
    int gemm_blocks = (N_NODES + GBM - 1) / GBM;               // 782
    gat_gemm_hmma<<<gemm_blocks, 512, GEMM_SMEM_BYTES>>>(x, W, b, att_l, att_r, N_NODES);

    // 2) edge lift: persistent, 4 CTAs/SM, grid-stride (R10 config)
    int edge_blocks = 148 * 4;                                 // 592
    edge_lift_kernel<<<edge_blocks, 256>>>(src, trg, out_alpha, out_x, N_EDGES);
}

// round 15
// speedup vs baseline: 1.1189x; 1.1189x over previous
#include <cuda_runtime.h>
#include <cuda_bf16.h>
#include <cstdint>

// Problem constants
#define N_NODES 100000
#define N_EDGES 1638400
#define IN_CH   128
#define HEADS   4
#define OUT_CH  32
#define OUTF    (HEADS * OUT_CH)   // 128

// Scratch (allowed: __device__ globals, no allocation)
__device__ float g_h [(size_t)N_NODES * OUTF];   // 51.2 MB, L2-resident
__device__ float g_al[(size_t)N_NODES * HEADS];
__device__ float g_ar[(size_t)N_NODES * HEADS];

// ===========================================================================
// Kernel 1: h = x @ W^T + b via mma.sync bf16 3-term split (R13 structure —
// 256 threads / 8 warps / 64x32 warp tile — plus ldmatrix fragment loads:
// 6 LDSM.x4 per warp per k-step instead of 24 scalar LDS).
//   h = x_hi*W_hi + x_hi*W_lo + x_lo*W_hi  (fp32 accumulate)
// ===========================================================================
#define GBM 128
#define ASTR 272            // bf16 tile row stride in bytes — LDSM conflict-free
#define TILE_BYTES (128 * ASTR)   // 34816

// dynamic smem layout (bytes)
#define SO_BIAS 0
#define SO_ATTL 512
#define SO_ATTR 1024
#define SO_AHI  1536
#define SO_ALO  (SO_AHI + TILE_BYTES)
#define SO_WHI  (SO_ALO + TILE_BYTES)
#define SO_WLO  (SO_WHI + TILE_BYTES)
#define GEMM_SMEM_BYTES (SO_WLO + TILE_BYTES)   // 140800
#define DS 132              // D staging row stride (floats), overlays SO_AHI

__device__ __forceinline__ void mma_bf16_16816(float d[4],
                                               uint32_t a0, uint32_t a1,
                                               uint32_t a2, uint32_t a3,
                                               uint32_t b0, uint32_t b1) {
    asm volatile(
        "mma.sync.aligned.m16n8k16.row.col.f32.bf16.bf16.f32 "
        "{%0,%1,%2,%3}, {%4,%5,%6,%7}, {%8,%9}, {%0,%1,%2,%3};"
        : "+f"(d[0]), "+f"(d[1]), "+f"(d[2]), "+f"(d[3])
        : "r"(a0), "r"(a1), "r"(a2), "r"(a3), "r"(b0), "r"(b1));
}

__device__ __forceinline__ void ldsm4(uint32_t& r0, uint32_t& r1,
                                      uint32_t& r2, uint32_t& r3, uint32_t addr) {
    asm volatile("ldmatrix.sync.aligned.m8n8.x4.shared.b16 {%0,%1,%2,%3}, [%4];"
                 : "=r"(r0), "=r"(r1), "=r"(r2), "=r"(r3) : "r"(addr));
}

// convert 8 floats -> bf16 hi/lo packed uint4s
__device__ __forceinline__ void cvt_hilo8(const float* f, uint4& hiv, uint4& lov) {
    uint32_t hi[4], lo[4];
    #pragma unroll
    for (int j = 0; j < 4; j++) {
        __nv_bfloat162 h2 = __floats2bfloat162_rn(f[2*j], f[2*j+1]);
        float2 hf = __bfloat1622float2(h2);
        __nv_bfloat162 l2 = __floats2bfloat162_rn(f[2*j] - hf.x, f[2*j+1] - hf.y);
        hi[j] = *reinterpret_cast<uint32_t*>(&h2);
        lo[j] = *reinterpret_cast<uint32_t*>(&l2);
    }
    hiv = make_uint4(hi[0], hi[1], hi[2], hi[3]);
    lov = make_uint4(lo[0], lo[1], lo[2], lo[3]);
}

__global__ void __launch_bounds__(256)
gat_gemm_hmma(const float* __restrict__ x,
              const float* __restrict__ W,
              const float* __restrict__ b,
              const float* __restrict__ att_l,
              const float* __restrict__ att_r,
              int nrows)
{
    extern __shared__ char smem[];
    const int tid  = threadIdx.x;
    const int row0 = blockIdx.x * GBM;

    // ---- params to smem ----
    if (tid < 128) {
        ((float*)(smem + SO_BIAS))[tid] = b[tid];
        ((float*)(smem + SO_ATTL))[tid] = att_l[tid];
        ((float*)(smem + SO_ATTR))[tid] = att_r[tid];
    }

    // ---- convert x tile and W to bf16 hi/lo (each thread: one (row, half)) ----
    {
        const int row  = tid >> 1;
        const int half = tid & 1;
        const int grow = row0 + row;
        const bool xvalid = (grow < nrows);

        #pragma unroll
        for (int i = 0; i < 8; i++) {
            const int k0 = half * 64 + i * 8;
            // x slice
            float f[8];
            if (xvalid) {
                const float4* p = reinterpret_cast<const float4*>(x + (size_t)grow * IN_CH + k0);
                float4 v0 = p[0], v1 = p[1];
                f[0]=v0.x; f[1]=v0.y; f[2]=v0.z; f[3]=v0.w;
                f[4]=v1.x; f[5]=v1.y; f[6]=v1.z; f[7]=v1.w;
            } else {
                #pragma unroll
                for (int j = 0; j < 8; j++) f[j] = 0.f;
            }
            uint4 hiv, lov;
            cvt_hilo8(f, hiv, lov);
            const int off = row * ASTR + k0 * 2;   // 16B aligned
            *reinterpret_cast<uint4*>(smem + SO_AHI + off) = hiv;
            *reinterpret_cast<uint4*>(smem + SO_ALO + off) = lov;

            // W slice (row = output channel; always valid)
            const float4* q = reinterpret_cast<const float4*>(W + (size_t)row * IN_CH + k0);
            float4 w0 = q[0], w1 = q[1];
            float g[8] = { w0.x, w0.y, w0.z, w0.w, w1.x, w1.y, w1.z, w1.w };
            cvt_hilo8(g, hiv, lov);
            *reinterpret_cast<uint4*>(smem + SO_WHI + off) = hiv;
            *reinterpret_cast<uint4*>(smem + SO_WLO + off) = lov;
        }
    }
    __syncthreads();

    // ---- MMA mainloop: 8 warps, warp tile 64x32, LDSM fragment loads ----
    const int wid  = tid >> 5;
    const int lane = tid & 31;
    const int wm = (wid & 1) * 64;        // warp m origin
    const int wn = (wid >> 1) * 32;       // warp n origin
    const int li   = lane & 7;            // row within 8x8 matrix
    const int quad = lane >> 3;           // which of the 4 matrices

    // LDSM relative byte offsets (within a tile buffer)
    uint32_t a_rel[4], b_rel[2];
    #pragma unroll
    for (int mt = 0; mt < 4; mt++)
        a_rel[mt] = (uint32_t)((wm + mt * 16 + (quad & 1) * 8 + li) * ASTR + (quad >> 1) * 16);
    #pragma unroll
    for (int p = 0; p < 2; p++)
        b_rel[p] = (uint32_t)((wn + p * 16 + (quad >> 1) * 8 + li) * ASTR + (quad & 1) * 16);

    const uint32_t sAHI = (uint32_t)__cvta_generic_to_shared(smem + SO_AHI);
    const uint32_t sALO = (uint32_t)__cvta_generic_to_shared(smem + SO_ALO);
    const uint32_t sWHI = (uint32_t)__cvta_generic_to_shared(smem + SO_WHI);
    const uint32_t sWLO = (uint32_t)__cvta_generic_to_shared(smem + SO_WLO);

    float d[4][4][4];
    #pragma unroll
    for (int mt = 0; mt < 4; mt++)
        #pragma unroll
        for (int nt = 0; nt < 4; nt++)
            #pragma unroll
            for (int e = 0; e < 4; e++) d[mt][nt][e] = 0.f;

    #pragma unroll
    for (int s = 0; s < 3; s++) {
        const uint32_t As = (s == 2) ? sALO : sAHI;
        const uint32_t Bs = (s == 1) ? sWLO : sWHI;
        #pragma unroll
        for (int ks = 0; ks < 8; ks++) {
            const uint32_t k0b = ks * 32;   // 16 bf16 = 32 bytes per k-step
            uint32_t a[4][4], bb[4][2];
            #pragma unroll
            for (int mt = 0; mt < 4; mt++)
                ldsm4(a[mt][0], a[mt][1], a[mt][2], a[mt][3], As + a_rel[mt] + k0b);
            ldsm4(bb[0][0], bb[0][1], bb[1][0], bb[1][1], Bs + b_rel[0] + k0b);
            ldsm4(bb[2][0], bb[2][1], bb[3][0], bb[3][1], Bs + b_rel[1] + k0b);
            #pragma unroll
            for (int mt = 0; mt < 4; mt++)
                #pragma unroll
                for (int nt = 0; nt < 4; nt++)
                    mma_bf16_16816(d[mt][nt], a[mt][0], a[mt][1], a[mt][2], a[mt][3],
                                   bb[nt][0], bb[nt][1]);
        }
    }
    __syncthreads();   // A/W tiles dead; stage D over SO_AHI region

    const int gr = lane >> 2;             // 0..7
    const int kq = (lane & 3) * 2;        // 0,2,4,6
    float* Dst = (float*)(smem + SO_AHI); // [128][DS]
    #pragma unroll
    for (int mt = 0; mt < 4; mt++) {
        #pragma unroll
        for (int nt = 0; nt < 4; nt++) {
            const int r = wm + mt * 16 + gr;
            const int c = wn + nt * 8 + kq;
            *reinterpret_cast<float2*>(Dst + r * DS + c)       = make_float2(d[mt][nt][0], d[mt][nt][1]);
            *reinterpret_cast<float2*>(Dst + (r + 8) * DS + c) = make_float2(d[mt][nt][2], d[mt][nt][3]);
        }
    }
    __syncthreads();

    // ---- epilogue: thread = (row, half); bias add, g_h store, alpha dots ----
    {
        const int row  = tid >> 1;
        const int half = tid & 1;
        const int grow = row0 + row;
        if (grow < nrows) {
            const float* sbias = (const float*)(smem + SO_BIAS);
            const float* sattl = (const float*)(smem + SO_ATTL);
            const float* sattr = (const float*)(smem + SO_ATTR);
            float sl0 = 0.f, sr0 = 0.f, sl1 = 0.f, sr1 = 0.f;
            #pragma unroll
            for (int q = 0; q < 16; q++) {         // 16 float4 chunks = 64 cols
                float4 v;
                float* vp = &v.x;
                #pragma unroll
                for (int e = 0; e < 4; e++) {
                    const int gc = half * 64 + q * 4 + e;
                    float val = Dst[row * DS + gc] + sbias[gc];
                    vp[e] = val;
                    if (q < 8) { sl0 += val * sattl[gc]; sr0 += val * sattr[gc]; }
                    else       { sl1 += val * sattl[gc]; sr1 += val * sattr[gc]; }
                }
                *reinterpret_cast<float4*>(g_h + (size_t)grow * OUTF + half * 64 + q * 4) = v;
            }
            const int h0 = half * 2;
            *reinterpret_cast<float2*>(g_al + (size_t)grow * HEADS + h0) = make_float2(sl0, sl1);
            *reinterpret_cast<float2*>(g_ar + (size_t)grow * HEADS + h0) = make_float2(sr0, sr1);
        }
    }
}

// ===========================================================================
// Kernel 2: edge lift — exact R10 configuration (measured 186-190us):
// persistent grid-stride, 8 edges/warp/iter, plain __ldg gathers,
// __ldcs index loads, .cs streaming output stores, 4 CTAs/SM.
// ===========================================================================
#define EPW 8   // edges per warp per iteration (N_EDGES % EPW == 0)

__global__ void __launch_bounds__(256, 4)
edge_lift_kernel(const int* __restrict__ src_idx,
                 const int* __restrict__ trg_idx,
                 float* __restrict__ out_alpha,
                 float* __restrict__ out_x,
                 int nedges)
{
    const int lane   = threadIdx.x & 31;
    const int nwarps = (gridDim.x * blockDim.x) >> 5;
    const int gw     = (blockIdx.x * blockDim.x + threadIdx.x) >> 5;

    for (long long base = (long long)gw * EPW; base < nedges;
         base += (long long)nwarps * EPW) {

        int sidx = 0, tidx = 0;
        if (lane < EPW) {
            sidx = __ldcs(src_idx + base + lane);   // streaming: read-once
            tidx = __ldcs(trg_idx + base + lane);
        }

        int s[EPW];
        #pragma unroll
        for (int u = 0; u < EPW; u++)
            s[u] = __shfl_sync(0xffffffffu, sidx, u);

        // EPW independent gathers (MLP=EPW), L2-resident g_h
        float4 v[EPW];
        #pragma unroll
        for (int u = 0; u < EPW; u++)
            v[u] = *reinterpret_cast<const float4*>(g_h + (size_t)s[u] * OUTF + lane * 4);

        #pragma unroll
        for (int u = 0; u < EPW; u++)
            __stcs(reinterpret_cast<float4*>(out_x + (base + u) * OUTF + lane * 4), v[u]);

        if (lane < EPW) {
            float4 al = *reinterpret_cast<const float4*>(g_al + (size_t)sidx * HEADS);
            float4 ar = *reinterpret_cast<const float4*>(g_ar + (size_t)tidx * HEADS);
            float4 a;
            a.x = al.x + ar.x; a.x = (a.x >= 0.f) ? a.x : 0.01f * a.x;
            a.y = al.y + ar.y; a.y = (a.y >= 0.f) ? a.y : 0.01f * a.y;
            a.z = al.z + ar.z; a.z = (a.z >= 0.f) ? a.z : 0.01f * a.z;
            a.w = al.w + ar.w; a.w = (a.w >= 0.f) ? a.w : 0.01f * a.w;
            __stcs(reinterpret_cast<float4*>(out_alpha + (base + lane) * HEADS), a);
        }
    }
}

// ---------------------------------------------------------------------------
// Launch
// ---------------------------------------------------------------------------
extern "C" void kernel_launch(void* const* d_in, const int* in_sizes, int n_in,
                              void* d_out, int out_size)
{
    const float* x     = (const float*)d_in[0];   // [N, 128]
    const float* W     = (const float*)d_in[1];   // [128, 128]
    const float* b     = (const float*)d_in[2];   // [128]
    const float* att_l = (const float*)d_in[3];   // [1,4,32] -> flat 128
    const float* att_r = (const float*)d_in[4];   // [1,4,32] -> flat 128
    const int*   src   = (const int*)d_in[5];     // [E]
    const int*   trg   = (const int*)d_in[6];     // [E]

    float* out_alpha = (float*)d_out;                                   // [E, 4]
    float* out_x     = (float*)d_out + (size_t)N_EDGES * HEADS;         // [E, 4, 32]

    // >48KB dynamic smem opt-in (idempotent; harmless outside capture)
    cudaFuncSetAttribute(gat_gemm_hmma,
                         cudaFuncAttributeMaxDynamicSharedMemorySize,
                         GEMM_SMEM_BYTES);

    // 1) HMMA projection GEMM into g_h (+ fused alpha_l/alpha_r)
    int gemm_blocks = (N_NODES + GBM - 1) / GBM;               // 782
    gat_gemm_hmma<<<gemm_blocks, 256, GEMM_SMEM_BYTES>>>(x, W, b, att_l, att_r, N_NODES);

    // 2) edge lift: persistent, 4 CTAs/SM, grid-stride (R10 config)
    int edge_blocks = 148 * 4;                                 // 592
    edge_lift_kernel<<<edge_blocks, 256>>>(src, trg, out_alpha, out_x, N_EDGES);
}